// round 5
// baseline (speedup 1.0000x reference)
#include <cuda_runtime.h>
#include <cuda_bf16.h>

#define NN 60000
#define EE 240000
#define GG 512

// ---------------- scratch layout (floats) ----------------
// X12  : N*12   padded input features
// GC   : N*32   interleaved [g1(16) | c1(16)] per node
// AGG1 : N*64   [a*x(12) | e0*x | e1*x | e2*x | 1*x (each 12) | pad 4]   (self-restoring zero)
// AGG2 : N*80   [a*g1(16) | e0*c1 | e1*c1 | e2*c1 | 1*c1 (each 16)]     (self-restoring zero)
// POOL : G*64   [g2 pooled(32) | c2 pooled(32)]                          (self-restoring zero)
constexpr int OFF_X12  = 0;
constexpr int OFF_GC   = OFF_X12 + NN * 12;
constexpr int OFF_AGG1 = OFF_GC  + NN * 32;
constexpr int OFF_AGG2 = OFF_AGG1 + NN * 64;
constexpr int OFF_POOL = OFF_AGG2 + NN * 80;
constexpr int SCRATCH_TOTAL = OFF_POOL + GG * 64;

__device__ __align__(16) float d_scratch[SCRATCH_TOTAL];

// bf16 hi/lo split weight tables (built by init each call)
// W2: [96 rows -> 64 outputs], stored transposed [n=64][k=96]
// W1: [80 rows -> 32 outputs], stored transposed [n=32][k=80]
__device__ __align__(16) __nv_bfloat16 d_W2hi[64 * 96];
__device__ __align__(16) __nv_bfloat16 d_W2lo[64 * 96];
__device__ __align__(16) __nv_bfloat16 d_W1hi[32 * 80];
__device__ __align__(16) __nv_bfloat16 d_W1lo[32 * 80];

// ---------------- helpers ----------------
__device__ __forceinline__ void red_add_v4(float* addr, float4 v) {
    asm volatile("red.global.add.v4.f32 [%0], {%1, %2, %3, %4};"
                 :: "l"(addr), "f"(v.x), "f"(v.y), "f"(v.z), "f"(v.w)
                 : "memory");
}
__device__ __forceinline__ void red_add_f(float* addr, float v) {
    asm volatile("red.global.add.f32 [%0], %1;" :: "l"(addr), "f"(v) : "memory");
}

// pack float2 -> bf16x2 (low half = .x), also produce lo-residual pack
__device__ __forceinline__ unsigned split_bf16x2(float2 v, unsigned& lo) {
    unsigned hi;
    asm("cvt.rn.bf16x2.f32 %0, %1, %2;" : "=r"(hi) : "f"(v.y), "f"(v.x));
    float hx = __uint_as_float(hi << 16);
    float hy = __uint_as_float(hi & 0xffff0000u);
    float rx = v.x - hx, ry = v.y - hy;
    asm("cvt.rn.bf16x2.f32 %0, %1, %2;" : "=r"(lo) : "f"(ry), "f"(rx));
    return hi;
}

__device__ __forceinline__ void mma_bf16(float* d, const unsigned* a, unsigned b0, unsigned b1) {
    asm volatile(
        "mma.sync.aligned.m16n8k16.row.col.f32.bf16.bf16.f32 "
        "{%0,%1,%2,%3}, {%4,%5,%6,%7}, {%8,%9}, {%0,%1,%2,%3};"
        : "+f"(d[0]), "+f"(d[1]), "+f"(d[2]), "+f"(d[3])
        : "r"(a[0]), "r"(a[1]), "r"(a[2]), "r"(a[3]), "r"(b0), "r"(b1));
}

// ---------------- init: build X12 + bf16 weight tables ----------------
__global__ void init_kernel(const float* __restrict__ x,
                            const float* __restrict__ Wg1,
                            const float* __restrict__ We1, const float* __restrict__ be1,
                            const float* __restrict__ root1,
                            const float* __restrict__ Wg2,
                            const float* __restrict__ We2, const float* __restrict__ be2,
                            const float* __restrict__ root2) {
    int i = blockIdx.x * blockDim.x + threadIdx.x;
    if (i < NN * 3) {
        int node = i / 3, p = i - node * 3;
        int f0 = p * 4;
        const float* xr = x + node * 10;
        float4 v;
        v.x = (f0 + 0 < 10) ? xr[f0 + 0] : 0.f;
        v.y = (f0 + 1 < 10) ? xr[f0 + 1] : 0.f;
        v.z = (f0 + 2 < 10) ? xr[f0 + 2] : 0.f;
        v.w = (f0 + 3 < 10) ? xr[f0 + 3] : 0.f;
        ((float4*)(d_scratch + OFF_X12))[node * 3 + p] = v;
        return;
    }
    int j = i - NN * 3;
    if (j < 64 * 96) {
        // W2t[n][r]: rows 0:16 -> Wg2 (outputs 0:32); 16:80 -> We2/be2 (outputs 32:64);
        //            80:96 -> root2 (outputs 32:64)
        int n = j / 96, r = j - n * 96;
        float w = 0.f;
        if (r < 16) {
            if (n < 32) w = Wg2[r * 32 + n];
        } else if (r < 80) {
            if (n >= 32) {
                int s = (r - 16) >> 4, f = (r - 16) & 15, o = n - 32;
                w = (s < 3) ? We2[s * 512 + f * 32 + o] : be2[f * 32 + o];
            }
        } else {
            if (n >= 32) w = root2[(r - 80) * 32 + (n - 32)];
        }
        __nv_bfloat16 hi = __float2bfloat16(w);
        __nv_bfloat16 lo = __float2bfloat16(w - __bfloat162float(hi));
        d_W2hi[j] = hi; d_W2lo[j] = lo;
        return;
    }
    int m = j - 64 * 96;
    if (m < 32 * 80) {
        // W1t[n][r]: rows 0:12 -> Wg1 (outputs 0:16); 12:60 -> We1/be1 (outputs 16:32);
        //            64:76 -> root1 (outputs 16:32); rest 0
        int n = m / 80, r = m - n * 80;
        float w = 0.f;
        if (r < 12) {
            if (n < 16 && r < 10) w = Wg1[r * 16 + n];
        } else if (r < 60) {
            if (n >= 16) {
                int s = (r - 12) / 12, f = (r - 12) % 12;
                if (f < 10) {
                    int o = n - 16;
                    w = (s < 3) ? We1[s * 160 + f * 16 + o] : be1[f * 16 + o];
                }
            }
        } else if (r >= 64 && r < 76) {
            if (n >= 16 && (r - 64) < 10) w = root1[(r - 64) * 16 + (n - 16)];
        }
        __nv_bfloat16 hi = __float2bfloat16(w);
        __nv_bfloat16 lo = __float2bfloat16(w - __bfloat162float(hi));
        d_W1hi[m] = hi; d_W1lo[m] = lo;
    }
}

// ---------------- pass1: scatter coeff*x12 into AGG1 ----------------
__global__ void pass1_kernel(const int* __restrict__ ei,
                             const float* __restrict__ av,
                             const float* __restrict__ ef) {
    int t = blockIdx.x * blockDim.x + threadIdx.x;
    int edge = t / 5;
    int q = t - edge * 5;
    if (edge >= EE) return;
    int row = ei[edge];
    int col = ei[EE + edge];
    float coeff;
    if (q == 0)      coeff = av[edge];
    else if (q < 4)  coeff = ef[edge * 3 + (q - 1)];
    else             coeff = 1.f;
    const float4* xp = (const float4*)(d_scratch + OFF_X12 + col * 12);
    float* dst = d_scratch + OFF_AGG1 + row * 64 + q * 12;
#pragma unroll
    for (int k = 0; k < 3; k++) {
        float4 v = xp[k];
        red_add_v4(dst + k * 4,
                   make_float4(coeff * v.x, coeff * v.y, coeff * v.z, coeff * v.w));
    }
}

// ---------------- post1: [128x80] x [80x32] tensor GEMM -> GC, re-zero AGG1 ----------------
__device__ __forceinline__ float2 ldA1(int row, int c) {
    if (row >= NN) return make_float2(0.f, 0.f);
    if (c < 64) return *(const float2*)(d_scratch + OFF_AGG1 + row * 64 + c);
    int cc = c - 64;
    if (cc < 12) return *(const float2*)(d_scratch + OFF_X12 + row * 12 + cc);
    return make_float2(0.f, 0.f);
}

__global__ __launch_bounds__(128) void post1_kernel(const float* __restrict__ bg1,
                                                    const float* __restrict__ bias1) {
    __shared__ float sBias[32];
    int tid = threadIdx.x, lane = tid & 31, w = tid >> 5;
    if (tid < 32) sBias[tid] = (tid < 16) ? bg1[tid] : bias1[tid - 16];
    __syncthreads();
    int tb = blockIdx.x * 128;
    int rbase = tb + w * 32 + (lane >> 2);
    int koff = (lane & 3) * 2;

    float acc[2][4][4];
#pragma unroll
    for (int mt = 0; mt < 2; mt++)
#pragma unroll
        for (int n = 0; n < 4; n++)
#pragma unroll
            for (int r = 0; r < 4; r++) acc[mt][n][r] = 0.f;

#pragma unroll
    for (int k = 0; k < 5; k++) {
        unsigned ahi[2][4], alo[2][4];
#pragma unroll
        for (int mt = 0; mt < 2; mt++) {
            int r0 = rbase + mt * 16, r1 = r0 + 8;
            int c = k * 16 + koff;
            ahi[mt][0] = split_bf16x2(ldA1(r0, c),     alo[mt][0]);
            ahi[mt][1] = split_bf16x2(ldA1(r1, c),     alo[mt][1]);
            ahi[mt][2] = split_bf16x2(ldA1(r0, c + 8), alo[mt][2]);
            ahi[mt][3] = split_bf16x2(ldA1(r1, c + 8), alo[mt][3]);
        }
#pragma unroll
        for (int n = 0; n < 4; n++) {
            int ncol = n * 8 + (lane >> 2);
            const unsigned* ph = (const unsigned*)(d_W1hi + ncol * 80 + k * 16 + koff);
            const unsigned* pl = (const unsigned*)(d_W1lo + ncol * 80 + k * 16 + koff);
            unsigned bh0 = ph[0], bh1 = ph[4];
            unsigned bl0 = pl[0], bl1 = pl[4];
#pragma unroll
            for (int mt = 0; mt < 2; mt++) {
                mma_bf16(acc[mt][n], ahi[mt], bh0, bh1);
                mma_bf16(acc[mt][n], ahi[mt], bl0, bl1);
                mma_bf16(acc[mt][n], alo[mt], bh0, bh1);
            }
        }
    }
    // re-zero AGG1 rows owned by this warp (16 float4 per row)
    for (int i = lane; i < 32 * 16; i += 32) {
        int row = tb + w * 32 + (i >> 4);
        if (row < NN)
            ((float4*)(d_scratch + OFF_AGG1 + row * 64))[i & 15] =
                make_float4(0.f, 0.f, 0.f, 0.f);
    }
    // epilogue: relu(acc + bias) -> GC[row*32 + col]
#pragma unroll
    for (int mt = 0; mt < 2; mt++) {
        int r0 = rbase + mt * 16, r1 = r0 + 8;
#pragma unroll
        for (int n = 0; n < 4; n++) {
            int c0 = n * 8 + koff;
            if (r0 < NN) {
                d_scratch[OFF_GC + r0 * 32 + c0]     = fmaxf(acc[mt][n][0] + sBias[c0], 0.f);
                d_scratch[OFF_GC + r0 * 32 + c0 + 1] = fmaxf(acc[mt][n][1] + sBias[c0 + 1], 0.f);
            }
            if (r1 < NN) {
                d_scratch[OFF_GC + r1 * 32 + c0]     = fmaxf(acc[mt][n][2] + sBias[c0], 0.f);
                d_scratch[OFF_GC + r1 * 32 + c0 + 1] = fmaxf(acc[mt][n][3] + sBias[c0 + 1], 0.f);
            }
        }
    }
}

// ---------------- pass2: scatter coeff*(g1|c1) into AGG2 ----------------
__global__ void pass2_kernel(const int* __restrict__ ei,
                             const float* __restrict__ av,
                             const float* __restrict__ ef) {
    int t = blockIdx.x * blockDim.x + threadIdx.x;
    int edge = t >> 2, q = t & 3;
    if (edge >= EE) return;
    int row = ei[edge];
    int col = ei[EE + edge];
    float a  = av[edge];
    float e0 = ef[edge * 3 + 0], e1 = ef[edge * 3 + 1], e2 = ef[edge * 3 + 2];
    const float4* gc = (const float4*)(d_scratch + OFF_GC + col * 32);
    float4 g1v = gc[q];
    float4 c1v = gc[4 + q];
    float* base = d_scratch + OFF_AGG2 + row * 80;
    red_add_v4(base + q * 4, make_float4(a * g1v.x, a * g1v.y, a * g1v.z, a * g1v.w));
    float coeffs[4] = {e0, e1, e2, 1.f};
#pragma unroll
    for (int s = 0; s < 4; s++) {
        float c = coeffs[s];
        red_add_v4(base + 16 + s * 16 + q * 4,
                   make_float4(c * c1v.x, c * c1v.y, c * c1v.z, c * c1v.w));
    }
}

// ---------------- post2: [128x96] x [96x64] tensor GEMM + pool, re-zero AGG2 ----------------
__device__ __forceinline__ float2 ldA2(int row, int c) {
    if (row >= NN) return make_float2(0.f, 0.f);
    if (c < 80) return *(const float2*)(d_scratch + OFF_AGG2 + row * 80 + c);
    return *(const float2*)(d_scratch + OFF_GC + row * 32 + 16 + (c - 80));
}

__global__ __launch_bounds__(128) void post2_kernel(const int* __restrict__ seg,
                                                    const float* __restrict__ bg2,
                                                    const float* __restrict__ bias2) {
    __shared__ float sPool[8][64];
    __shared__ float sBias[64];
    int tid = threadIdx.x, lane = tid & 31, w = tid >> 5;
    for (int i = tid; i < 512; i += 128) ((float*)sPool)[i] = 0.f;
    if (tid < 64) sBias[tid] = (tid < 32) ? bg2[tid] : bias2[tid - 32];
    __syncthreads();
    int tb = blockIdx.x * 128;
    int seg0 = seg[tb];
    int rbase = tb + w * 32 + (lane >> 2);
    int koff = (lane & 3) * 2;

    float acc[2][8][4];
#pragma unroll
    for (int mt = 0; mt < 2; mt++)
#pragma unroll
        for (int n = 0; n < 8; n++)
#pragma unroll
            for (int r = 0; r < 4; r++) acc[mt][n][r] = 0.f;

#pragma unroll
    for (int k = 0; k < 6; k++) {
        unsigned ahi[2][4], alo[2][4];
#pragma unroll
        for (int mt = 0; mt < 2; mt++) {
            int r0 = rbase + mt * 16, r1 = r0 + 8;
            int c = k * 16 + koff;
            ahi[mt][0] = split_bf16x2(ldA2(r0, c),     alo[mt][0]);
            ahi[mt][1] = split_bf16x2(ldA2(r1, c),     alo[mt][1]);
            ahi[mt][2] = split_bf16x2(ldA2(r0, c + 8), alo[mt][2]);
            ahi[mt][3] = split_bf16x2(ldA2(r1, c + 8), alo[mt][3]);
        }
#pragma unroll
        for (int n = 0; n < 8; n++) {
            int ncol = n * 8 + (lane >> 2);
            const unsigned* ph = (const unsigned*)(d_W2hi + ncol * 96 + k * 16 + koff);
            const unsigned* pl = (const unsigned*)(d_W2lo + ncol * 96 + k * 16 + koff);
            unsigned bh0 = ph[0], bh1 = ph[4];
            unsigned bl0 = pl[0], bl1 = pl[4];
#pragma unroll
            for (int mt = 0; mt < 2; mt++) {
                mma_bf16(acc[mt][n], ahi[mt], bh0, bh1);
                mma_bf16(acc[mt][n], ahi[mt], bl0, bl1);
                mma_bf16(acc[mt][n], alo[mt], bh0, bh1);
            }
        }
    }
    // re-zero AGG2 rows owned by this warp (20 float4 per row)
    for (int i = lane; i < 32 * 20; i += 32) {
        int row = tb + w * 32 + i / 20;
        if (row < NN)
            ((float4*)(d_scratch + OFF_AGG2 + row * 80))[i % 20] =
                make_float4(0.f, 0.f, 0.f, 0.f);
    }
    // epilogue: relu(acc + bias) -> pool by graph (seg sorted -> few slots per tile)
#pragma unroll
    for (int mt = 0; mt < 2; mt++) {
        int r0 = rbase + mt * 16, r1 = r0 + 8;
        int s0 = (r0 < NN) ? (seg[r0] - seg0) : -1;
        int s1 = (r1 < NN) ? (seg[r1] - seg0) : -1;
#pragma unroll
        for (int n = 0; n < 8; n++) {
            int c0 = n * 8 + koff;
            float v0 = fmaxf(acc[mt][n][0] + sBias[c0], 0.f);
            float v1 = fmaxf(acc[mt][n][1] + sBias[c0 + 1], 0.f);
            float v2 = fmaxf(acc[mt][n][2] + sBias[c0], 0.f);
            float v3 = fmaxf(acc[mt][n][3] + sBias[c0 + 1], 0.f);
            if (s0 >= 0) {
                if (s0 < 8) {
                    atomicAdd(&sPool[s0][c0], v0);
                    atomicAdd(&sPool[s0][c0 + 1], v1);
                } else {
                    red_add_f(d_scratch + OFF_POOL + seg[r0] * 64 + c0, v0);
                    red_add_f(d_scratch + OFF_POOL + seg[r0] * 64 + c0 + 1, v1);
                }
            }
            if (s1 >= 0) {
                if (s1 < 8) {
                    atomicAdd(&sPool[s1][c0], v2);
                    atomicAdd(&sPool[s1][c0 + 1], v3);
                } else {
                    red_add_f(d_scratch + OFF_POOL + seg[r1] * 64 + c0, v2);
                    red_add_f(d_scratch + OFF_POOL + seg[r1] * 64 + c0 + 1, v3);
                }
            }
        }
    }
    __syncthreads();
    for (int i = tid; i < 512; i += 128) {
        float v = ((float*)sPool)[i];
        if (v != 0.f) {
            int slot = i >> 6, col = i & 63;
            int g = seg0 + slot;
            if (g < GG) red_add_f(d_scratch + OFF_POOL + g * 64 + col, v);
        }
    }
}

// ---------------- head: MLP + sigmoid, re-zero POOL ----------------
__global__ void head_kernel(const float* __restrict__ Wd1, const float* __restrict__ bd1,
                            const float* __restrict__ Wd2, const float* __restrict__ bd2,
                            const float* __restrict__ Wo,  const float* __restrict__ bo,
                            float* __restrict__ out) {
    __shared__ float sW1[64 * 16];
    __shared__ float sb1[16];
    __shared__ float sW2[16 * 8];
    __shared__ float sb2[8];
    __shared__ float sWo[8];
    for (int i = threadIdx.x; i < 1024; i += blockDim.x) sW1[i] = Wd1[i];
    if (threadIdx.x < 16)  sb1[threadIdx.x] = bd1[threadIdx.x];
    if (threadIdx.x < 128) sW2[threadIdx.x] = Wd2[threadIdx.x];
    if (threadIdx.x < 8)   { sb2[threadIdx.x] = bd2[threadIdx.x]; sWo[threadIdx.x] = Wo[threadIdx.x]; }
    __syncthreads();
    int g = blockIdx.x * blockDim.x + threadIdx.x;
    if (g >= GG) return;
    float* pr = d_scratch + OFF_POOL + g * 64;
    float h1[16];
#pragma unroll
    for (int k = 0; k < 16; k++) h1[k] = sb1[k];
    for (int f = 0; f < 64; f++) {
        float v = pr[f];
#pragma unroll
        for (int k = 0; k < 16; k++) h1[k] += v * sW1[f * 16 + k];
    }
#pragma unroll
    for (int k = 0; k < 16; k++) h1[k] = fmaxf(h1[k], 0.f);
    float h2[8];
#pragma unroll
    for (int m = 0; m < 8; m++) h2[m] = sb2[m];
#pragma unroll
    for (int k = 0; k < 16; k++) {
        float v = h1[k];
#pragma unroll
        for (int m = 0; m < 8; m++) h2[m] += v * sW2[k * 8 + m];
    }
    float z = bo[0];
#pragma unroll
    for (int m = 0; m < 8; m++) z += fmaxf(h2[m], 0.f) * sWo[m];
    out[g] = 1.f / (1.f + expf(-z));
    // self-restoring zero for next replay
    float4* pz = (float4*)pr;
#pragma unroll
    for (int k = 0; k < 16; k++) pz[k] = make_float4(0.f, 0.f, 0.f, 0.f);
}

// ---------------- launch ----------------
extern "C" void kernel_launch(void* const* d_in, const int* in_sizes, int n_in,
                              void* d_out, int out_size) {
    const float* x     = (const float*)d_in[0];
    const float* av    = (const float*)d_in[1];
    const float* ef    = (const float*)d_in[2];
    const int*   ei    = (const int*)  d_in[3];
    const int*   seg   = (const int*)  d_in[4];
    const float* Wg1   = (const float*)d_in[5];
    const float* bg1   = (const float*)d_in[6];
    const float* Wg2   = (const float*)d_in[7];
    const float* bg2   = (const float*)d_in[8];
    const float* We1   = (const float*)d_in[9];
    const float* be1   = (const float*)d_in[10];
    const float* root1 = (const float*)d_in[11];
    const float* bias1 = (const float*)d_in[12];
    const float* We2   = (const float*)d_in[13];
    const float* be2   = (const float*)d_in[14];
    const float* root2 = (const float*)d_in[15];
    const float* bias2 = (const float*)d_in[16];
    const float* Wd1   = (const float*)d_in[17];
    const float* bd1   = (const float*)d_in[18];
    const float* Wd2   = (const float*)d_in[19];
    const float* bd2   = (const float*)d_in[20];
    const float* Wo    = (const float*)d_in[21];
    const float* bo    = (const float*)d_in[22];
    float* out = (float*)d_out;

    constexpr int INIT_ITEMS = NN * 3 + 64 * 96 + 32 * 80;
    constexpr int NTILES = (NN + 127) / 128;
    init_kernel<<<(INIT_ITEMS + 255) / 256, 256>>>(x, Wg1, We1, be1, root1,
                                                   Wg2, We2, be2, root2);
    pass1_kernel<<<(EE * 5 + 319) / 320, 320>>>(ei, av, ef);
    post1_kernel<<<NTILES, 128>>>(bg1, bias1);
    pass2_kernel<<<(EE * 4 + 255) / 256, 256>>>(ei, av, ef);
    post2_kernel<<<NTILES, 128>>>(seg, bg2, bias2);
    head_kernel<<<2, 256>>>(Wd1, bd1, Wd2, bd2, Wo, bo, out);
}

// round 6
// speedup vs baseline: 1.3069x; 1.3069x over previous
#include <cuda_runtime.h>

#define NN 60000
#define EE 240000
#define GG 512

// ---------------- scratch layout (floats) ----------------
// A1  : NN rows, stride 80:  [agg q*12+f (q<5, 60 used, 60..63 pad=0) | x12 (64..75) | pad]
//       agg part self-restoring-zeroed by post1; x12 rebuilt by init each call.
// NS  : NN rows, stride 112: [g1(0..15) | c1(16..31) | agg a*g1(32..47) | agg e'(x)c1 (48..111)]
//       agg part (32..111) self-restoring-zeroed by post2; g1/c1 overwritten by post1.
// POOL: GG*64  [g2-pool(32) | c2-pool(32)]  self-restoring-zeroed by head.
constexpr int OFF_A1   = 0;
constexpr int OFF_NS   = OFF_A1 + NN * 80;
constexpr int OFF_POOL = OFF_NS + NN * 112;
constexpr int SCRATCH_TOTAL = OFF_POOL + GG * 64;

__device__ __align__(16) float d_scratch[SCRATCH_TOTAL];

// ---------------- helpers ----------------
__device__ __forceinline__ void red_add_v4(float* addr, float4 v) {
    asm volatile("red.global.add.v4.f32 [%0], {%1, %2, %3, %4};"
                 :: "l"(addr), "f"(v.x), "f"(v.y), "f"(v.z), "f"(v.w)
                 : "memory");
}
__device__ __forceinline__ void red_add_f(float* addr, float v) {
    asm volatile("red.global.add.f32 [%0], %1;" :: "l"(addr), "f"(v) : "memory");
}

typedef unsigned long long ull;

__device__ __forceinline__ ull pk2(float lo, float hi) {
    ull r;
    asm("mov.b64 %0, {%1, %2};" : "=l"(r) : "f"(lo), "f"(hi));
    return r;
}
__device__ __forceinline__ void fma2(ull& acc, ull a, ull b) {
    asm("fma.rn.f32x2 %0, %1, %2, %0;" : "+l"(acc) : "l"(a), "l"(b));
}
__device__ __forceinline__ float2 upk(ull v) {
    float2 o;
    asm("mov.b64 {%0, %1}, %2;" : "=f"(o.x), "=f"(o.y) : "l"(v));
    return o;
}

// ---------------- init: write x12 into A1 rows ----------------
__global__ void init_kernel(const float* __restrict__ x) {
    int n = blockIdx.x * blockDim.x + threadIdx.x;
    if (n >= NN) return;
    const float* xr = x + n * 10;
    float f[16];
#pragma unroll
    for (int i = 0; i < 10; i++) f[i] = xr[i];
#pragma unroll
    for (int i = 10; i < 16; i++) f[i] = 0.f;
    float4* dst = (float4*)(d_scratch + OFF_A1 + n * 80 + 64);
#pragma unroll
    for (int k = 0; k < 4; k++)
        dst[k] = make_float4(f[4 * k], f[4 * k + 1], f[4 * k + 2], f[4 * k + 3]);
}

// ---------------- pass1: scatter coeff*x12 into A1 agg ----------------
__global__ void pass1_kernel(const int* __restrict__ ei,
                             const float* __restrict__ av,
                             const float* __restrict__ ef) {
    int t = blockIdx.x * blockDim.x + threadIdx.x;
    int edge = t / 5;
    int q = t - edge * 5;
    if (edge >= EE) return;
    int row = ei[edge];
    int col = ei[EE + edge];
    float coeff;
    if (q == 0)      coeff = av[edge];
    else if (q < 4)  coeff = ef[edge * 3 + (q - 1)];
    else             coeff = 1.f;
    const float4* xp = (const float4*)(d_scratch + OFF_A1 + col * 80 + 64);
    float* dst = d_scratch + OFF_A1 + row * 80 + q * 12;
#pragma unroll
    for (int k = 0; k < 3; k++) {
        float4 v = xp[k];
        red_add_v4(dst + k * 4,
                   make_float4(coeff * v.x, coeff * v.y, coeff * v.z, coeff * v.w));
    }
}

// ---------------- post1: staged contraction -> g1,c1 in NS; re-zero A1 agg ----------------
__global__ __launch_bounds__(128) void post1_kernel(const float* __restrict__ Wg1,
                                                    const float* __restrict__ bg1,
                                                    const float* __restrict__ We1,
                                                    const float* __restrict__ be1,
                                                    const float* __restrict__ root1,
                                                    const float* __restrict__ bias1) {
    extern __shared__ float sA[];                 // [128][81]
    __shared__ __align__(16) float sWg1[160];     // [f<10][o<16]
    __shared__ __align__(16) float sK[640];       // [s<4][f<10][o<16] (s=3 -> be1)
    __shared__ __align__(16) float sR[160];       // [f<10][o<16]
    __shared__ float sBg[16], sB1[16];
    int tid = threadIdx.x;
    int tb = blockIdx.x * 128;
    for (int i = tid; i < 160; i += 128) { sWg1[i] = Wg1[i]; sR[i] = root1[i]; }
    for (int i = tid; i < 640; i += 128) sK[i] = (i < 480) ? We1[i] : be1[i - 480];
    if (tid < 16) { sBg[tid] = bg1[tid]; sB1[tid] = bias1[tid]; }
    // stage tile (coalesced)
    for (int i = tid; i < 2560; i += 128) {
        int flat = i * 4;
        int node = flat / 80, k = flat - node * 80;
        float4 v = make_float4(0.f, 0.f, 0.f, 0.f);
        if (tb + node < NN)
            v = *(const float4*)(d_scratch + OFF_A1 + (tb + node) * 80 + k);
        float* s = &sA[node * 81 + k];
        s[0] = v.x; s[1] = v.y; s[2] = v.z; s[3] = v.w;
    }
    __syncthreads();
    // re-zero agg portion (coalesced)
    for (int i = tid; i < 2560; i += 128) {
        int flat = i * 4;
        int node = flat / 80, k = flat - node * 80;
        if (k < 64 && tb + node < NN)
            *(float4*)(d_scratch + OFF_A1 + (tb + node) * 80 + k) =
                make_float4(0.f, 0.f, 0.f, 0.f);
    }
    int node = tb + tid;
    ull ga[8], ca[8];
#pragma unroll
    for (int k = 0; k < 8; k++) {
        ga[k] = pk2(sBg[2 * k], sBg[2 * k + 1]);
        ca[k] = pk2(sB1[2 * k], sB1[2 * k + 1]);
    }
    const float* Ar = &sA[tid * 81];
    // gcn: k = f (q=0)
#pragma unroll
    for (int f = 0; f < 10; f++) {
        ull s = pk2(Ar[f], Ar[f]);
        const ulonglong2* w = (const ulonglong2*)&sWg1[f * 16];
#pragma unroll
        for (int k = 0; k < 4; k++) {
            ulonglong2 wp = w[k];
            fma2(ga[2 * k], s, wp.x);
            fma2(ga[2 * k + 1], s, wp.y);
        }
    }
    // ecc: q=1..4 -> s_i=q-1
#pragma unroll
    for (int q = 1; q < 5; q++) {
#pragma unroll
        for (int f = 0; f < 10; f++) {
            ull s = pk2(Ar[q * 12 + f], Ar[q * 12 + f]);
            const ulonglong2* w = (const ulonglong2*)&sK[(q - 1) * 160 + f * 16];
#pragma unroll
            for (int k = 0; k < 4; k++) {
                ulonglong2 wp = w[k];
                fma2(ca[2 * k], s, wp.x);
                fma2(ca[2 * k + 1], s, wp.y);
            }
        }
    }
    // root: x12 at cols 64..73
#pragma unroll
    for (int f = 0; f < 10; f++) {
        ull s = pk2(Ar[64 + f], Ar[64 + f]);
        const ulonglong2* w = (const ulonglong2*)&sR[f * 16];
#pragma unroll
        for (int k = 0; k < 4; k++) {
            ulonglong2 wp = w[k];
            fma2(ca[2 * k], s, wp.x);
            fma2(ca[2 * k + 1], s, wp.y);
        }
    }
    if (node < NN) {
        float4* o = (float4*)(d_scratch + OFF_NS + node * 112);
#pragma unroll
        for (int k = 0; k < 4; k++) {
            float2 a0 = upk(ga[2 * k]), a1 = upk(ga[2 * k + 1]);
            o[k] = make_float4(fmaxf(a0.x, 0.f), fmaxf(a0.y, 0.f),
                               fmaxf(a1.x, 0.f), fmaxf(a1.y, 0.f));
            float2 b0 = upk(ca[2 * k]), b1 = upk(ca[2 * k + 1]);
            o[4 + k] = make_float4(fmaxf(b0.x, 0.f), fmaxf(b0.y, 0.f),
                                   fmaxf(b1.x, 0.f), fmaxf(b1.y, 0.f));
        }
    }
}

// ---------------- pass2: scatter coeff*(g1|c1) into NS agg ----------------
__global__ void pass2_kernel(const int* __restrict__ ei,
                             const float* __restrict__ av,
                             const float* __restrict__ ef) {
    int t = blockIdx.x * blockDim.x + threadIdx.x;
    int edge = t >> 2, q = t & 3;
    if (edge >= EE) return;
    int row = ei[edge];
    int col = ei[EE + edge];
    float a  = av[edge];
    float e0 = ef[edge * 3 + 0], e1 = ef[edge * 3 + 1], e2 = ef[edge * 3 + 2];
    const float4* src = (const float4*)(d_scratch + OFF_NS + col * 112);
    float4 g1v = src[q];
    float4 c1v = src[4 + q];
    float* base = d_scratch + OFF_NS + row * 112 + 32;
    red_add_v4(base + q * 4, make_float4(a * g1v.x, a * g1v.y, a * g1v.z, a * g1v.w));
    float coeffs[4] = {e0, e1, e2, 1.f};
#pragma unroll
    for (int s = 0; s < 4; s++) {
        float c = coeffs[s];
        red_add_v4(base + 16 + s * 16 + q * 4,
                   make_float4(c * c1v.x, c * c1v.y, c * c1v.z, c * c1v.w));
    }
}

// ---------------- post2: staged contraction + segment pool; re-zero NS agg ----------------
__global__ __launch_bounds__(128) void post2_kernel(const int* __restrict__ seg,
                                                    const float* __restrict__ Wg2,
                                                    const float* __restrict__ bg2,
                                                    const float* __restrict__ We2,
                                                    const float* __restrict__ be2,
                                                    const float* __restrict__ root2,
                                                    const float* __restrict__ bias2) {
    extern __shared__ float sA[];                 // [128][97], window cols 16..111 of NS
    __shared__ __align__(16) float sWg2[512];     // [f<16][o<32]
    __shared__ __align__(16) float sK2[2048];     // [s<4][f<16][o<32] (s=3 -> be2)
    __shared__ __align__(16) float sR2[512];      // [f<16][o<32]
    __shared__ float sBg[32], sB2[32];
    __shared__ int sSeg[128];
    int tid = threadIdx.x;
    int tb = blockIdx.x * 128;
    for (int i = tid; i < 512; i += 128) { sWg2[i] = Wg2[i]; sR2[i] = root2[i]; }
    for (int i = tid; i < 2048; i += 128) sK2[i] = (i < 1536) ? We2[i] : be2[i - 1536];
    if (tid < 32) { sBg[tid] = bg2[tid]; sB2[tid] = bias2[tid]; }
    {
        int n = tb + tid;
        sSeg[tid] = seg[n < NN ? n : (NN - 1)];
    }
    // stage window [node][16..111] (coalesced-ish)
    for (int i = tid; i < 3072; i += 128) {
        int flat = i * 4;
        int node = flat / 96, k = flat - node * 96;
        float4 v = make_float4(0.f, 0.f, 0.f, 0.f);
        if (tb + node < NN)
            v = *(const float4*)(d_scratch + OFF_NS + (tb + node) * 112 + 16 + k);
        float* s = &sA[node * 97 + k];
        s[0] = v.x; s[1] = v.y; s[2] = v.z; s[3] = v.w;
    }
    __syncthreads();
    // re-zero agg portion NS[32..111] (coalesced)
    for (int i = tid; i < 2560; i += 128) {
        int flat = i * 4;
        int node = flat / 80, k = flat - node * 80;
        if (tb + node < NN)
            *(float4*)(d_scratch + OFF_NS + (tb + node) * 112 + 32 + k) =
                make_float4(0.f, 0.f, 0.f, 0.f);
    }
    ull ga[16], ca[16];
#pragma unroll
    for (int k = 0; k < 16; k++) {
        ga[k] = pk2(sBg[2 * k], sBg[2 * k + 1]);
        ca[k] = pk2(sB2[2 * k], sB2[2 * k + 1]);
    }
    float* Ar = &sA[tid * 97];
    // g2: window cols 16..31 = a*g1 agg
#pragma unroll
    for (int f = 0; f < 16; f++) {
        ull s = pk2(Ar[16 + f], Ar[16 + f]);
        const ulonglong2* w = (const ulonglong2*)&sWg2[f * 32];
#pragma unroll
        for (int k = 0; k < 8; k++) {
            ulonglong2 wp = w[k];
            fma2(ga[2 * k], s, wp.x);
            fma2(ga[2 * k + 1], s, wp.y);
        }
    }
    // c2 root: window cols 0..15 = c1
#pragma unroll
    for (int f = 0; f < 16; f++) {
        ull s = pk2(Ar[f], Ar[f]);
        const ulonglong2* w = (const ulonglong2*)&sR2[f * 32];
#pragma unroll
        for (int k = 0; k < 8; k++) {
            ulonglong2 wp = w[k];
            fma2(ca[2 * k], s, wp.x);
            fma2(ca[2 * k + 1], s, wp.y);
        }
    }
    // c2 ecc: window cols 32..95, s-major
#pragma unroll
    for (int si = 0; si < 4; si++) {
#pragma unroll
        for (int f = 0; f < 16; f++) {
            ull s = pk2(Ar[32 + si * 16 + f], Ar[32 + si * 16 + f]);
            const ulonglong2* w = (const ulonglong2*)&sK2[si * 512 + f * 32];
#pragma unroll
            for (int k = 0; k < 8; k++) {
                ulonglong2 wp = w[k];
                fma2(ca[2 * k], s, wp.x);
                fma2(ca[2 * k + 1], s, wp.y);
            }
        }
    }
    // relu + write own out row into sA[tid][0..63]  (own row only -> safe pre-sync)
    bool valid = (tb + tid) < NN;
#pragma unroll
    for (int k = 0; k < 16; k++) {
        float2 a = upk(ga[k]);
        Ar[2 * k]     = valid ? fmaxf(a.x, 0.f) : 0.f;
        Ar[2 * k + 1] = valid ? fmaxf(a.y, 0.f) : 0.f;
        float2 b = upk(ca[k]);
        Ar[32 + 2 * k]     = valid ? fmaxf(b.x, 0.f) : 0.f;
        Ar[32 + 2 * k + 1] = valid ? fmaxf(b.y, 0.f) : 0.f;
    }
    __syncthreads();
    // segmented column sum (seg sorted): thread = (col, half)
    int col = tid & 63, half = tid >> 6;
    int r0 = half * 64;
    float acc = 0.f;
    int cur = sSeg[r0];
    for (int r = r0; r < r0 + 64; r++) {
        int sg = sSeg[r];
        if (sg != cur) {
            red_add_f(d_scratch + OFF_POOL + cur * 64 + col, acc);
            acc = 0.f;
            cur = sg;
        }
        acc += sA[r * 97 + col];
    }
    red_add_f(d_scratch + OFF_POOL + cur * 64 + col, acc);
}

// ---------------- head: MLP + sigmoid; re-zero POOL ----------------
__global__ void head_kernel(const float* __restrict__ Wd1, const float* __restrict__ bd1,
                            const float* __restrict__ Wd2, const float* __restrict__ bd2,
                            const float* __restrict__ Wo,  const float* __restrict__ bo,
                            float* __restrict__ out) {
    __shared__ float sW1[64 * 16];
    __shared__ float sb1[16];
    __shared__ float sW2[16 * 8];
    __shared__ float sb2[8];
    __shared__ float sWo[8];
    for (int i = threadIdx.x; i < 1024; i += blockDim.x) sW1[i] = Wd1[i];
    if (threadIdx.x < 16)  sb1[threadIdx.x] = bd1[threadIdx.x];
    if (threadIdx.x < 128) sW2[threadIdx.x] = Wd2[threadIdx.x];
    if (threadIdx.x < 8)   { sb2[threadIdx.x] = bd2[threadIdx.x]; sWo[threadIdx.x] = Wo[threadIdx.x]; }
    __syncthreads();
    int g = blockIdx.x * blockDim.x + threadIdx.x;
    if (g >= GG) return;
    float* pr = d_scratch + OFF_POOL + g * 64;
    float h1[16];
#pragma unroll
    for (int k = 0; k < 16; k++) h1[k] = sb1[k];
    for (int f = 0; f < 64; f++) {
        float v = pr[f];
#pragma unroll
        for (int k = 0; k < 16; k++) h1[k] += v * sW1[f * 16 + k];
    }
#pragma unroll
    for (int k = 0; k < 16; k++) h1[k] = fmaxf(h1[k], 0.f);
    float h2[8];
#pragma unroll
    for (int m = 0; m < 8; m++) h2[m] = sb2[m];
#pragma unroll
    for (int k = 0; k < 16; k++) {
        float v = h1[k];
#pragma unroll
        for (int m = 0; m < 8; m++) h2[m] += v * sW2[k * 8 + m];
    }
    float z = bo[0];
#pragma unroll
    for (int m = 0; m < 8; m++) z += fmaxf(h2[m], 0.f) * sWo[m];
    out[g] = 1.f / (1.f + expf(-z));
    // self-restoring zero for next replay
    float4* pz = (float4*)pr;
#pragma unroll
    for (int k = 0; k < 16; k++) pz[k] = make_float4(0.f, 0.f, 0.f, 0.f);
}

// ---------------- launch ----------------
extern "C" void kernel_launch(void* const* d_in, const int* in_sizes, int n_in,
                              void* d_out, int out_size) {
    const float* x     = (const float*)d_in[0];
    const float* av    = (const float*)d_in[1];
    const float* ef    = (const float*)d_in[2];
    const int*   ei    = (const int*)  d_in[3];
    const int*   seg   = (const int*)  d_in[4];
    const float* Wg1   = (const float*)d_in[5];
    const float* bg1   = (const float*)d_in[6];
    const float* Wg2   = (const float*)d_in[7];
    const float* bg2   = (const float*)d_in[8];
    const float* We1   = (const float*)d_in[9];
    const float* be1   = (const float*)d_in[10];
    const float* root1 = (const float*)d_in[11];
    const float* bias1 = (const float*)d_in[12];
    const float* We2   = (const float*)d_in[13];
    const float* be2   = (const float*)d_in[14];
    const float* root2 = (const float*)d_in[15];
    const float* bias2 = (const float*)d_in[16];
    const float* Wd1   = (const float*)d_in[17];
    const float* bd1   = (const float*)d_in[18];
    const float* Wd2   = (const float*)d_in[19];
    const float* bd2   = (const float*)d_in[20];
    const float* Wo    = (const float*)d_in[21];
    const float* bo    = (const float*)d_in[22];
    float* out = (float*)d_out;

    constexpr int NTILES = (NN + 127) / 128;
    constexpr int SMEM1 = 128 * 81 * 4;   // 41472 B
    constexpr int SMEM2 = 128 * 97 * 4;   // 49664 B (> 48K -> needs attr)
    cudaFuncSetAttribute(post2_kernel, cudaFuncAttributeMaxDynamicSharedMemorySize, SMEM2);

    init_kernel<<<(NN + 255) / 256, 256>>>(x);
    pass1_kernel<<<(EE * 5 + 319) / 320, 320>>>(ei, av, ef);
    post1_kernel<<<NTILES, 128, SMEM1>>>(Wg1, bg1, We1, be1, root1, bias1);
    pass2_kernel<<<(EE * 4 + 255) / 256, 256>>>(ei, av, ef);
    post2_kernel<<<NTILES, 128, SMEM2>>>(seg, Wg2, bg2, We2, be2, root2, bias2);
    head_kernel<<<2, 256>>>(Wd1, bd1, Wd2, bd2, Wo, bo, out);
}